// round 1
// baseline (speedup 1.0000x reference)
#include <cuda_runtime.h>
#include <cstdint>

// Problem constants
#define NN   32
#define CIN  64
#define COUTC 64
#define REDC 2
#define TT   64
#define VV   128
#define KK   (REDC*TT)   // 128

// Scratch (device globals; no allocation allowed)
__device__ float g_xf[NN*COUTC*TT*VV];   // [n][o][t][v]  67 MB
__device__ float g_a [NN*KK*VV];         // [n][k][v]      2 MB
__device__ float g_b [NN*KK*VV];         // [n][k][w]      2 MB
__device__ float g_xm[(size_t)NN*TT*VV*VV]; // [n][t][v][w] 134 MB
__device__ float g_WrmT[KK*TT];          // [k][t]

// tanh(x) = 1 - 2/(1+e^{2x}) via MUFU.EX2 + MUFU.RCP (abs err ~1e-6)
__device__ __forceinline__ float fast_tanh(float x) {
    float e;
    asm("ex2.approx.f32 %0, %1;" : "=f"(e) : "f"(x * 2.885390081777927f));
    float r;
    asm("rcp.approx.f32 %0, %1;" : "=f"(r) : "f"(e + 1.0f));
    return 1.0f - 2.0f * r;
}

// ---------------------------------------------------------------------------
// kT: transpose Wrm [t][k] -> g_WrmT [k][t]
// ---------------------------------------------------------------------------
__global__ void kT(const float* __restrict__ Wrm) {
    int i = blockIdx.x * blockDim.x + threadIdx.x;   // 8192 total
    if (i < KK*TT) {
        int t = i >> 7;          // /128
        int k = i & 127;
        g_WrmT[k*TT + t] = Wrm[i];   // read coalesced, scattered write (one-time, tiny)
    }
}

// ---------------------------------------------------------------------------
// kA: per (n,t): thread v holds x[n,:,t,v] in registers.
//   xf[n,o,t,v] = sum_c Wf[o,c] x[n,c,t,v] + bf[o]
//   a[n, r*T+t, v] = sum_c Wm1[r,c] x + bm1[r];   b likewise with Wm2
// ---------------------------------------------------------------------------
__global__ void __launch_bounds__(128) kA(
    const float* __restrict__ x,
    const float* __restrict__ Wf,  const float* __restrict__ bf,
    const float* __restrict__ Wm1, const float* __restrict__ bm1,
    const float* __restrict__ Wm2, const float* __restrict__ bm2)
{
    __shared__ float WfT[CIN*68];     // [c][o] padded stride 68 (float4-aligned)
    __shared__ float w1s[REDC*CIN];
    __shared__ float w2s[REDC*CIN];

    const int tid = threadIdx.x;
    const int t = blockIdx.x;
    const int n = blockIdx.y;

    // Load Wf transposed: iterate o fastest -> conflict-free smem writes.
    for (int e = tid; e < COUTC*CIN; e += 128) {
        int o = e & 63, c = e >> 6;
        WfT[c*68 + o] = Wf[o*CIN + c];    // reads strided (L1/L2 resident, tiny)
    }
    for (int e = tid; e < REDC*CIN; e += 128) { w1s[e] = Wm1[e]; w2s[e] = Wm2[e]; }
    __syncthreads();

    const int v = tid;
    // x[n,c,t,v] base
    const float* xp = x + ((size_t)n*CIN*TT + t)*VV + v;
    float xv[CIN];
    #pragma unroll
    for (int c = 0; c < CIN; c++) xv[c] = xp[(size_t)c*TT*VV];   // coalesced over v

    // small 1x1 convs -> a, b
    #pragma unroll
    for (int r = 0; r < REDC; r++) {
        float s1 = bm1[r], s2 = bm2[r];
        #pragma unroll
        for (int c = 0; c < CIN; c++) {
            s1 += w1s[r*CIN + c] * xv[c];
            s2 += w2s[r*CIN + c] * xv[c];
        }
        size_t idx = ((size_t)n*KK + r*TT + t)*VV + v;
        g_a[idx] = s1;
        g_b[idx] = s2;
    }

    // xf: 4 outputs at a time (float4 broadcast from WfT)
    #pragma unroll 1
    for (int o0 = 0; o0 < COUTC; o0 += 4) {
        float a0 = bf[o0], a1 = bf[o0+1], a2 = bf[o0+2], a3 = bf[o0+3];
        #pragma unroll
        for (int c = 0; c < CIN; c++) {
            float4 wv = *(const float4*)&WfT[c*68 + o0];
            a0 += wv.x * xv[c];
            a1 += wv.y * xv[c];
            a2 += wv.z * xv[c];
            a3 += wv.w * xv[c];
        }
        size_t base = (((size_t)n*COUTC + o0)*TT + t)*VV + v;
        g_xf[base]              = a0;
        g_xf[base + TT*VV]      = a1;
        g_xf[base + 2*TT*VV]    = a2;
        g_xf[base + 3*TT*VV]    = a3;
    }
}

// ---------------------------------------------------------------------------
// kB: xm[n,t,v,w] = brm[t] + A[t,v,w] + sum_k WrmT[k][t] * tanh(a[n,k,v]-b[n,k,w])
// Block: one n, 8 v's, 32 w's. Thread: one (v,w), 64 t-accumulators.
// Dynamic smem: WrmT 32KB + a 4KB + b 16KB = 52KB
// ---------------------------------------------------------------------------
__global__ void __launch_bounds__(256) kB(
    const float* __restrict__ A, const float* __restrict__ brm)
{
    extern __shared__ float sm[];
    float* WT  = sm;             // [128][64]
    float* as_ = WT + KK*TT;     // [128][8]
    float* bs  = as_ + KK*8;     // [128][32]

    const int tid = threadIdx.x;
    const int n  = blockIdx.z;
    const int v0 = blockIdx.y * 8;
    const int w0 = blockIdx.x * 32;

    for (int e = tid; e < KK*TT; e += 256) WT[e] = g_WrmT[e];        // linear, coalesced
    for (int e = tid; e < KK*8; e += 256) {
        int vl = e & 7, k = e >> 3;
        as_[k*8 + vl] = g_a[((size_t)n*KK + k)*VV + v0 + vl];
    }
    for (int e = tid; e < KK*32; e += 256) {
        int wl = e & 31, k = e >> 5;
        bs[k*32 + wl] = g_b[((size_t)n*KK + k)*VV + w0 + wl];
    }
    __syncthreads();

    const int wl = tid & 31;     // warp-lane -> w (coalesced)
    const int vl = tid >> 5;     // warp id   -> v (broadcast reads)

    float acc[TT];
    #pragma unroll
    for (int t = 0; t < TT; t++) acc[t] = 0.0f;

    #pragma unroll 2
    for (int k = 0; k < KK; k++) {
        float d = fast_tanh(as_[k*8 + vl] - bs[k*32 + wl]);
        const float* wrow = &WT[k*TT];
        #pragma unroll
        for (int t4 = 0; t4 < TT/4; t4++) {
            float4 wv = *(const float4*)&wrow[t4*4];   // warp-uniform broadcast
            acc[t4*4+0] += wv.x * d;
            acc[t4*4+1] += wv.y * d;
            acc[t4*4+2] += wv.z * d;
            acc[t4*4+3] += wv.w * d;
        }
    }

    const int v = v0 + vl, w = w0 + wl;
    #pragma unroll
    for (int t = 0; t < TT; t++) {
        g_xm[(((size_t)n*TT + t)*VV + v)*VV + w] =
            acc[t] + brm[t] + A[((size_t)t*VV + v)*VV + w];
    }
}

// ---------------------------------------------------------------------------
// kC: out[n,c,t,w] = sum_v xf[n,c,t,v] * xm[n,t,v,w]
// Block: one (n,t). GEMM [64c x 128v] * [128v x 128w], v chunked by 32.
// Thread tile: 8c x 4w.
// ---------------------------------------------------------------------------
__global__ void __launch_bounds__(256) kC(float* __restrict__ out) {
    __shared__ float xfs[COUTC*32];    // [c][kk]
    __shared__ float xms[32*VV];       // [kk][w]

    const int tid = threadIdx.x;
    const int t = blockIdx.x;
    const int n = blockIdx.y;
    const int tx = tid & 31;   // -> w group (w = tx*4 .. +3)
    const int ty = tid >> 5;   // -> c group (c = ty*8 .. +7)

    float acc[8][4];
    #pragma unroll
    for (int i = 0; i < 8; i++)
        #pragma unroll
        for (int j = 0; j < 4; j++) acc[i][j] = 0.0f;

    for (int v0 = 0; v0 < VV; v0 += 32) {
        __syncthreads();
        for (int e = tid; e < COUTC*32; e += 256) {
            int kk = e & 31, c = e >> 5;
            xfs[e] = g_xf[(((size_t)n*COUTC + c)*TT + t)*VV + v0 + kk];
        }
        for (int e = tid; e < 32*VV; e += 256) {
            int w = e & 127, kk = e >> 7;
            xms[e] = g_xm[(((size_t)n*TT + t)*VV + v0 + kk)*VV + w];
        }
        __syncthreads();

        #pragma unroll 8
        for (int kk = 0; kk < 32; kk++) {
            float4 xm4 = *(const float4*)&xms[kk*VV + tx*4];
            #pragma unroll
            for (int ci = 0; ci < 8; ci++) {
                float xfv = xfs[(ty*8 + ci)*32 + kk];   // warp-uniform broadcast
                acc[ci][0] += xfv * xm4.x;
                acc[ci][1] += xfv * xm4.y;
                acc[ci][2] += xfv * xm4.z;
                acc[ci][3] += xfv * xm4.w;
            }
        }
    }

    #pragma unroll
    for (int ci = 0; ci < 8; ci++) {
        int c = ty*8 + ci;
        float4 r = make_float4(acc[ci][0], acc[ci][1], acc[ci][2], acc[ci][3]);
        *(float4*)&out[(((size_t)n*COUTC + c)*TT + t)*VV + tx*4] = r;
    }
}

// ---------------------------------------------------------------------------
extern "C" void kernel_launch(void* const* d_in, const int* in_sizes, int n_in,
                              void* d_out, int out_size)
{
    const float* x   = (const float*)d_in[0];
    const float* A   = (const float*)d_in[1];
    const float* Wf  = (const float*)d_in[2];
    const float* bf  = (const float*)d_in[3];
    const float* Wm1 = (const float*)d_in[4];
    const float* bm1 = (const float*)d_in[5];
    const float* Wm2 = (const float*)d_in[6];
    const float* bm2 = (const float*)d_in[7];
    const float* Wrm = (const float*)d_in[8];
    const float* brm = (const float*)d_in[9];
    float* out = (float*)d_out;

    const int kb_smem = (KK*TT + KK*8 + KK*32) * (int)sizeof(float);  // 53248
    cudaFuncSetAttribute(kB, cudaFuncAttributeMaxDynamicSharedMemorySize, kb_smem);

    kT<<<16, 512>>>(Wrm);
    kA<<<dim3(TT, NN), 128>>>(x, Wf, bf, Wm1, bm1, Wm2, bm2);
    kB<<<dim3(VV/32, VV/8, NN), 256, kb_smem>>>(A, brm);
    kC<<<dim3(TT, NN), 256>>>(out);
}

// round 2
// speedup vs baseline: 1.3470x; 1.3470x over previous
#include <cuda_runtime.h>
#include <cstdint>

// Problem constants
#define NN   32
#define CIN  64
#define COUTC 64
#define REDC 2
#define TT   64
#define VV   128
#define KK   (REDC*TT)   // 128
#define KC   16          // k-chunk for kB

// Scratch (device globals; no allocation allowed)
__device__ float g_xf[NN*COUTC*TT*VV];      // [n][o][t][v]  67 MB
__device__ float g_a [NN*KK*VV];            // [n][k][v]      2 MB
__device__ float g_b [NN*KK*VV];            // [n][k][w]      2 MB
__device__ float g_xm[(size_t)NN*TT*VV*VV]; // [n][t][v][w] 134 MB
__device__ float g_WrmT[KK*TT];             // [k][t]

// tanh(x) = 1 - 2/(1+e^{2x}) via MUFU.EX2 + MUFU.RCP (abs err ~1e-6)
__device__ __forceinline__ float fast_tanh(float x) {
    float e;
    asm("ex2.approx.f32 %0, %1;" : "=f"(e) : "f"(x * 2.885390081777927f));
    float r;
    asm("rcp.approx.f32 %0, %1;" : "=f"(r) : "f"(e + 1.0f));
    return 1.0f - 2.0f * r;
}

// ---------------------------------------------------------------------------
// kT: transpose Wrm [t][k] -> g_WrmT [k][t]
// ---------------------------------------------------------------------------
__global__ void kT(const float* __restrict__ Wrm) {
    int i = blockIdx.x * blockDim.x + threadIdx.x;
    if (i < KK*TT) {
        int t = i >> 7;
        int k = i & 127;
        g_WrmT[k*TT + t] = Wrm[i];
    }
}

// ---------------------------------------------------------------------------
// kA: per (n,t): thread v holds x[n,:,t,v] in registers.
// ---------------------------------------------------------------------------
__global__ void __launch_bounds__(128) kA(
    const float* __restrict__ x,
    const float* __restrict__ Wf,  const float* __restrict__ bf,
    const float* __restrict__ Wm1, const float* __restrict__ bm1,
    const float* __restrict__ Wm2, const float* __restrict__ bm2)
{
    __shared__ float WfT[CIN*68];
    __shared__ float w1s[REDC*CIN];
    __shared__ float w2s[REDC*CIN];

    const int tid = threadIdx.x;
    const int t = blockIdx.x;
    const int n = blockIdx.y;

    for (int e = tid; e < COUTC*CIN; e += 128) {
        int o = e & 63, c = e >> 6;
        WfT[c*68 + o] = Wf[o*CIN + c];
    }
    for (int e = tid; e < REDC*CIN; e += 128) { w1s[e] = Wm1[e]; w2s[e] = Wm2[e]; }
    __syncthreads();

    const int v = tid;
    const float* xp = x + ((size_t)n*CIN*TT + t)*VV + v;
    float xv[CIN];
    #pragma unroll
    for (int c = 0; c < CIN; c++) xv[c] = xp[(size_t)c*TT*VV];

    #pragma unroll
    for (int r = 0; r < REDC; r++) {
        float s1 = bm1[r], s2 = bm2[r];
        #pragma unroll
        for (int c = 0; c < CIN; c++) {
            s1 += w1s[r*CIN + c] * xv[c];
            s2 += w2s[r*CIN + c] * xv[c];
        }
        size_t idx = ((size_t)n*KK + r*TT + t)*VV + v;
        g_a[idx] = s1;
        g_b[idx] = s2;
    }

    #pragma unroll 1
    for (int o0 = 0; o0 < COUTC; o0 += 4) {
        float a0 = bf[o0], a1 = bf[o0+1], a2 = bf[o0+2], a3 = bf[o0+3];
        #pragma unroll
        for (int c = 0; c < CIN; c++) {
            float4 wv = *(const float4*)&WfT[c*68 + o0];
            a0 += wv.x * xv[c];
            a1 += wv.y * xv[c];
            a2 += wv.z * xv[c];
            a3 += wv.w * xv[c];
        }
        size_t base = (((size_t)n*COUTC + o0)*TT + t)*VV + v;
        g_xf[base]              = a0;
        g_xf[base + TT*VV]      = a1;
        g_xf[base + 2*TT*VV]    = a2;
        g_xf[base + 3*TT*VV]    = a3;
    }
}

// ---------------------------------------------------------------------------
// kB: xm[n,t,v,w] = brm[t] + A[t,v,w] + sum_k WrmT[k][t]*tanh(a[n,k,v]-b[n,k,w])
// Block: one n, 4 v's, 64 w's (vw tile = 256). Per k-chunk (KC=16):
//   phase 1: 256 threads compute d[16][256] tile (tanh) into smem
//   phase 2: register-tiled GEMM, thread = 8t x 8vw, 4 LDS128 : 64 FFMA per k
// ---------------------------------------------------------------------------
__global__ void __launch_bounds__(256) kB(
    const float* __restrict__ A, const float* __restrict__ brm)
{
    __shared__ float WT[KK*TT];   // [k][t] 32KB
    __shared__ float ds[KC*256];  // [kk][vw] 16KB

    const int tid = threadIdx.x;
    const int n  = blockIdx.z;
    const int v0 = blockIdx.y * 4;
    const int w0 = blockIdx.x * 64;

    for (int e = tid; e < KK*TT; e += 256) WT[e] = g_WrmT[e];

    // GEMM-phase mapping
    const int tg  = tid >> 5;          // 0..7  -> t = tg*8 .. +7
    const int vwg = tid & 31;          // 0..31 -> vw = vwg*8 .. +7

    // tanh-phase mapping: thread owns one k (of the chunk) and 16 consecutive vw
    const int kl  = tid >> 4;          // 0..15
    const int vwb = (tid & 15) * 16;   // 0..240, stays inside one v row
    const int tvl = vwb >> 6;          // v_local (0..3)
    const int twl = vwb & 63;          // w_local base

    float acc[8][8];
    #pragma unroll
    for (int i = 0; i < 8; i++)
        #pragma unroll
        for (int j = 0; j < 8; j++) acc[i][j] = 0.0f;

    for (int k0 = 0; k0 < KK; k0 += KC) {
        __syncthreads();   // prior GEMM phase done reading ds (also covers WT load)
        {
            const int k = k0 + kl;
            const float av = g_a[((size_t)n*KK + k)*VV + v0 + tvl];
            const float4* bp = (const float4*)&g_b[((size_t)n*KK + k)*VV + w0 + twl];
            float4* dp = (float4*)&ds[kl*256 + vwb];
            #pragma unroll
            for (int j = 0; j < 4; j++) {
                float4 bb = bp[j];
                float4 dd;
                dd.x = fast_tanh(av - bb.x);
                dd.y = fast_tanh(av - bb.y);
                dd.z = fast_tanh(av - bb.z);
                dd.w = fast_tanh(av - bb.w);
                dp[j] = dd;
            }
        }
        __syncthreads();

        #pragma unroll
        for (int kk = 0; kk < KC; kk++) {
            const int k = k0 + kk;
            float4 wlo = *(const float4*)&WT[k*TT + tg*8];       // warp-uniform
            float4 whi = *(const float4*)&WT[k*TT + tg*8 + 4];
            float4 dlo = *(const float4*)&ds[kk*256 + vwg*8];
            float4 dhi = *(const float4*)&ds[kk*256 + vwg*8 + 4];
            float wv[8] = {wlo.x, wlo.y, wlo.z, wlo.w, whi.x, whi.y, whi.z, whi.w};
            float dv[8] = {dlo.x, dlo.y, dlo.z, dlo.w, dhi.x, dhi.y, dhi.z, dhi.w};
            #pragma unroll
            for (int ti = 0; ti < 8; ti++)
                #pragma unroll
                for (int vi = 0; vi < 8; vi++)
                    acc[ti][vi] += wv[ti] * dv[vi];
        }
    }

    // Epilogue: thread's vw block = vwg*8..+7 -> fixed v row, 8 consecutive w
    const int v = v0 + (vwg >> 3);
    const int w = w0 + (vwg & 7) * 8;
    #pragma unroll
    for (int ti = 0; ti < 8; ti++) {
        const int t = tg*8 + ti;
        const float bt = __ldg(&brm[t]);
        const float4* Ap = (const float4*)&A[((size_t)t*VV + v)*VV + w];
        float4 A0 = Ap[0], A1 = Ap[1];
        float4 r0, r1;
        r0.x = acc[ti][0] + bt + A0.x;  r0.y = acc[ti][1] + bt + A0.y;
        r0.z = acc[ti][2] + bt + A0.z;  r0.w = acc[ti][3] + bt + A0.w;
        r1.x = acc[ti][4] + bt + A1.x;  r1.y = acc[ti][5] + bt + A1.y;
        r1.z = acc[ti][6] + bt + A1.z;  r1.w = acc[ti][7] + bt + A1.w;
        float4* op = (float4*)&g_xm[(((size_t)n*TT + t)*VV + v)*VV + w];
        op[0] = r0;
        op[1] = r1;
    }
}

// ---------------------------------------------------------------------------
// kC: out[n,c,t,w] = sum_v xf[n,c,t,v] * xm[n,t,v,w]
// Block: one (n,t). 64c x 128w output, K=v chunked by 32, kk blocked by 4:
// per 4-kk step: 12 LDS128 feed 128 FFMA.
// ---------------------------------------------------------------------------
__global__ void __launch_bounds__(256) kC(float* __restrict__ out) {
    __shared__ float xfs[COUTC*32];    // [c][kk]  8KB
    __shared__ float xms[32*VV];       // [kk][w] 16KB

    const int tid = threadIdx.x;
    const int t = blockIdx.x;
    const int n = blockIdx.y;
    const int tx = tid & 31;   // w = tx*4 .. +3
    const int ty = tid >> 5;   // c = ty*8 .. +7

    float acc[8][4];
    #pragma unroll
    for (int i = 0; i < 8; i++)
        #pragma unroll
        for (int j = 0; j < 4; j++) acc[i][j] = 0.0f;

    for (int v0 = 0; v0 < VV; v0 += 32) {
        __syncthreads();
        for (int e = tid; e < COUTC*32; e += 256) {
            int kk = e & 31, c = e >> 5;
            xfs[e] = g_xf[(((size_t)n*COUTC + c)*TT + t)*VV + v0 + kk];
        }
        for (int e = tid; e < 32*VV; e += 256) {
            int w = e & 127, kk = e >> 7;
            xms[e] = g_xm[(((size_t)n*TT + t)*VV + v0 + kk)*VV + w];
        }
        __syncthreads();

        #pragma unroll
        for (int kk4 = 0; kk4 < 8; kk4++) {
            float xfr[8][4];
            #pragma unroll
            for (int ci = 0; ci < 8; ci++) {
                float4 f = *(const float4*)&xfs[(ty*8 + ci)*32 + kk4*4];  // uniform
                xfr[ci][0] = f.x; xfr[ci][1] = f.y; xfr[ci][2] = f.z; xfr[ci][3] = f.w;
            }
            float xmr[4][4];
            #pragma unroll
            for (int j = 0; j < 4; j++) {
                float4 m = *(const float4*)&xms[(kk4*4 + j)*VV + tx*4];
                xmr[j][0] = m.x; xmr[j][1] = m.y; xmr[j][2] = m.z; xmr[j][3] = m.w;
            }
            #pragma unroll
            for (int j = 0; j < 4; j++)
                #pragma unroll
                for (int ci = 0; ci < 8; ci++) {
                    acc[ci][0] += xfr[ci][j] * xmr[j][0];
                    acc[ci][1] += xfr[ci][j] * xmr[j][1];
                    acc[ci][2] += xfr[ci][j] * xmr[j][2];
                    acc[ci][3] += xfr[ci][j] * xmr[j][3];
                }
        }
    }

    #pragma unroll
    for (int ci = 0; ci < 8; ci++) {
        int c = ty*8 + ci;
        float4 r = make_float4(acc[ci][0], acc[ci][1], acc[ci][2], acc[ci][3]);
        *(float4*)&out[(((size_t)n*COUTC + c)*TT + t)*VV + tx*4] = r;
    }
}

// ---------------------------------------------------------------------------
extern "C" void kernel_launch(void* const* d_in, const int* in_sizes, int n_in,
                              void* d_out, int out_size)
{
    const float* x   = (const float*)d_in[0];
    const float* A   = (const float*)d_in[1];
    const float* Wf  = (const float*)d_in[2];
    const float* bf  = (const float*)d_in[3];
    const float* Wm1 = (const float*)d_in[4];
    const float* bm1 = (const float*)d_in[5];
    const float* Wm2 = (const float*)d_in[6];
    const float* bm2 = (const float*)d_in[7];
    const float* Wrm = (const float*)d_in[8];
    const float* brm = (const float*)d_in[9];
    float* out = (float*)d_out;

    kT<<<16, 512>>>(Wrm);
    kA<<<dim3(TT, NN), 128>>>(x, Wf, bf, Wm1, bm1, Wm2, bm2);
    kB<<<dim3(VV/64, VV/4, NN), 256>>>(A, brm);
    kC<<<dim3(TT, NN), 256>>>(out);
}